// round 4
// baseline (speedup 1.0000x reference)
#include <cuda_runtime.h>
#include <cstdint>
#include <math.h>

#define EMBED 512
#define HID   1024
#define GATE  4096
#define BATCH 64
#define SEQ   256
#define MROWS (SEQ*BATCH)   // 16384

// Scratch (static device allocations — permitted; no runtime alloc).
__device__ float g_Xg[(size_t)MROWS * GATE];    // [T][B][4H] input projection + biases
__device__ float g_Hall[(size_t)MROWS * HID];   // [T][B][H] all hidden states
__device__ float g_h[BATCH * HID];
__device__ float g_c[BATCH * HID];

__device__ __forceinline__ float tf32r(float x) {
    asm("cvt.rna.tf32.f32 %0, %0;" : "+f"(x));
    return x;
}
__device__ __forceinline__ float4 tf32r4(float4 v) {
    v.x = tf32r(v.x); v.y = tf32r(v.y); v.z = tf32r(v.z); v.w = tf32r(v.w);
    return v;
}
__device__ __forceinline__ void mma8(float* c, const uint32_t* a, const uint32_t* b) {
    asm volatile("mma.sync.aligned.m16n8k8.row.col.f32.tf32.tf32.f32 "
                 "{%0,%1,%2,%3}, {%4,%5,%6,%7}, {%8,%9}, {%0,%1,%2,%3};"
                 : "+f"(c[0]), "+f"(c[1]), "+f"(c[2]), "+f"(c[3])
                 : "r"(a[0]), "r"(a[1]), "r"(a[2]), "r"(a[3]), "r"(b[0]), "r"(b[1]));
}
__device__ __forceinline__ float sigm(float x) { return 1.f / (1.f + expf(-x)); }

__global__ void init_state() {
    int i = blockIdx.x * blockDim.x + threadIdx.x;
    if (i < BATCH * HID) { g_h[i] = 0.f; g_c[i] = 0.f; }
}

// ---------------------------------------------------------------------------
// Generic tf32 GEMM:  C[m, n] = sum_k A[m,k] * W[n,k]  (+ bias)
// MODE 0 (pre):  A = embedded gathered by (t,b) row map, C = g_Xg direct,
//                bias = b_ih + b_hh, K = 512, N-grid covers 4096.
// MODE 1 (post): A = g_Hall direct, C = out scattered to [B][T][H],
//                bias = b_fc, K = 1024.
// BM=128, BN=64, BK=32, 256 threads (8 warps, 4x2), warp tile 32x32.
// ---------------------------------------------------------------------------
template<int MODE>
__launch_bounds__(256)
__global__ void gemm_tf32(const float* __restrict__ Ain,
                          const float* __restrict__ W,
                          const float* __restrict__ b1,
                          const float* __restrict__ b2,
                          float* __restrict__ Cout,
                          int K)
{
    extern __shared__ float sm[];
    float* As = sm;                 // 2 * 128*36 floats
    float* Bs = sm + 2 * 128 * 36;  // 2 * 64*36 floats

    const float* A = (MODE == 0) ? Ain : g_Hall;
    float* C       = (MODE == 0) ? g_Xg : Cout;

    const int tid  = threadIdx.x;
    const int warp = tid >> 5, lane = tid & 31;
    const int wm = warp >> 1, wn = warp & 1;
    const int g = lane >> 2, tg = lane & 3;
    const int mBase = blockIdx.x * 128;
    const int nBase = blockIdx.y * 64;
    const int nk = K >> 5;

    float acc[2][4][4];
#pragma unroll
    for (int a = 0; a < 2; a++)
#pragma unroll
        for (int b = 0; b < 4; b++)
#pragma unroll
            for (int cc = 0; cc < 4; cc++) acc[a][b][cc] = 0.f;

    float4 ar[4], br[2];

    // prologue: load k-tile 0 and stage to buffer 0
    {
#pragma unroll
        for (int i = 0; i < 4; i++) {
            int idx = tid + i * 256;
            int r = idx >> 3, k4 = idx & 7;
            int m = mBase + r;
            size_t aoff = (MODE == 0) ? ((size_t)((m & 63) * SEQ + (m >> 6)) * EMBED)
                                      : ((size_t)m * HID);
            ar[i] = *(const float4*)(A + aoff + k4 * 4);
        }
#pragma unroll
        for (int i = 0; i < 2; i++) {
            int idx = tid + i * 256;
            int r = idx >> 3, k4 = idx & 7;
            br[i] = *(const float4*)(W + (size_t)(nBase + r) * K + k4 * 4);
        }
#pragma unroll
        for (int i = 0; i < 4; i++) {
            int idx = tid + i * 256; int r = idx >> 3, k4 = idx & 7;
            *(float4*)(As + r * 36 + k4 * 4) = tf32r4(ar[i]);
        }
#pragma unroll
        for (int i = 0; i < 2; i++) {
            int idx = tid + i * 256; int r = idx >> 3, k4 = idx & 7;
            *(float4*)(Bs + r * 36 + k4 * 4) = tf32r4(br[i]);
        }
    }
    __syncthreads();

    for (int kt = 0; kt < nk; kt++) {
        if (kt + 1 < nk) {
            const int kB = (kt + 1) * 32;
#pragma unroll
            for (int i = 0; i < 4; i++) {
                int idx = tid + i * 256;
                int r = idx >> 3, k4 = idx & 7;
                int m = mBase + r;
                size_t aoff = (MODE == 0) ? ((size_t)((m & 63) * SEQ + (m >> 6)) * EMBED)
                                          : ((size_t)m * HID);
                ar[i] = *(const float4*)(A + aoff + kB + k4 * 4);
            }
#pragma unroll
            for (int i = 0; i < 2; i++) {
                int idx = tid + i * 256;
                int r = idx >> 3, k4 = idx & 7;
                br[i] = *(const float4*)(W + (size_t)(nBase + r) * K + kB + k4 * 4);
            }
        }
        const float* as = As + (kt & 1) * (128 * 36);
        const float* bs = Bs + (kt & 1) * (64 * 36);
#pragma unroll
        for (int ks = 0; ks < 4; ks++) {
            const int kk = ks * 8;
            uint32_t af[2][4], bf[4][2];
#pragma unroll
            for (int mt = 0; mt < 2; mt++) {
                int rb = wm * 32 + mt * 16;
                af[mt][0] = __float_as_uint(as[(rb + g    ) * 36 + kk + tg    ]);
                af[mt][1] = __float_as_uint(as[(rb + g + 8) * 36 + kk + tg    ]);
                af[mt][2] = __float_as_uint(as[(rb + g    ) * 36 + kk + tg + 4]);
                af[mt][3] = __float_as_uint(as[(rb + g + 8) * 36 + kk + tg + 4]);
            }
#pragma unroll
            for (int nt = 0; nt < 4; nt++) {
                int cb = wn * 32 + nt * 8;
                bf[nt][0] = __float_as_uint(bs[(cb + g) * 36 + kk + tg    ]);
                bf[nt][1] = __float_as_uint(bs[(cb + g) * 36 + kk + tg + 4]);
            }
#pragma unroll
            for (int mt = 0; mt < 2; mt++)
#pragma unroll
                for (int nt = 0; nt < 4; nt++)
                    mma8(acc[mt][nt], af[mt], bf[nt]);
        }
        if (kt + 1 < nk) {
            float* as2 = As + ((kt + 1) & 1) * (128 * 36);
            float* bs2 = Bs + ((kt + 1) & 1) * (64 * 36);
#pragma unroll
            for (int i = 0; i < 4; i++) {
                int idx = tid + i * 256; int r = idx >> 3, k4 = idx & 7;
                *(float4*)(as2 + r * 36 + k4 * 4) = tf32r4(ar[i]);
            }
#pragma unroll
            for (int i = 0; i < 2; i++) {
                int idx = tid + i * 256; int r = idx >> 3, k4 = idx & 7;
                *(float4*)(bs2 + r * 36 + k4 * 4) = tf32r4(br[i]);
            }
        }
        __syncthreads();
    }

    // epilogue: bias + store (c0/c1 and c2/c3 are column-adjacent -> float2)
#pragma unroll
    for (int mt = 0; mt < 2; mt++) {
#pragma unroll
        for (int nt = 0; nt < 4; nt++) {
            int row = mBase + wm * 32 + mt * 16 + g;
            int col = nBase + wn * 32 + nt * 8 + 2 * tg;
            float bv0 = b1[col], bv1 = b1[col + 1];
            if (MODE == 0) { bv0 += b2[col]; bv1 += b2[col + 1]; }
            size_t c0off, c2off;
            if (MODE == 0) {
                c0off = (size_t)row * GATE + col;
                c2off = (size_t)(row + 8) * GATE + col;
            } else {
                c0off = (size_t)((row & 63) * SEQ + (row >> 6)) * HID + col;
                c2off = (size_t)(((row + 8) & 63) * SEQ + ((row + 8) >> 6)) * HID + col;
            }
            *(float2*)(C + c0off) = make_float2(acc[mt][nt][0] + bv0, acc[mt][nt][1] + bv1);
            *(float2*)(C + c2off) = make_float2(acc[mt][nt][2] + bv0, acc[mt][nt][3] + bv1);
        }
    }
}

// ---------------------------------------------------------------------------
// One LSTM time step, fully fused: gates = h @ W_hh^T (tf32 mma) + Xg[t],
// then gate nonlinearities, c/h update, and h broadcast — single kernel.
// Grid: 128 CTAs; CTA owns 8 h-columns => 32 gate columns (i,f,g,o strips).
// 256 threads (8 warps 4x2), warp tile 16x16 of the 64x32 gate tile.
// W slice (32x1024) staged once in SMEM; h staged in 64x128 K-chunks.
// ---------------------------------------------------------------------------
__launch_bounds__(256)
__global__ void lstm_step(int t, const float* __restrict__ Whh)
{
    extern __shared__ float sm[];
    float* ws = sm;                 // 32 rows * 1028 (padded) floats
    float* hs = sm + 32 * 1028;     // 64 rows * 132 (padded) floats

    const int tid  = threadIdx.x;
    const int warp = tid >> 5, lane = tid & 31;
    const int wm = warp >> 1, wn = warp & 1;
    const int g = lane >> 2, tg = lane & 3;
    const int n0 = blockIdx.x * 8;

    // Stage W_hh slice (rows {n0+j, 1024+n0+j, 2048+n0+j, 3072+n0+j}), tf32-rounded.
    for (int i = tid; i < 32 * 256; i += 256) {   // float4 granularity
        int j = i >> 8, k4 = i & 255;
        int grow = (j >> 3) * HID + n0 + (j & 7);
        float4 v = tf32r4(*(const float4*)(Whh + (size_t)grow * HID + k4 * 4));
        *(float4*)(ws + j * 1028 + k4 * 4) = v;
    }

    float acc[2][4];
#pragma unroll
    for (int nt = 0; nt < 2; nt++)
#pragma unroll
        for (int cc = 0; cc < 4; cc++) acc[nt][cc] = 0.f;

    for (int kc = 0; kc < 8; kc++) {
        __syncthreads();            // protects hs reuse (and ws staging on kc==0)
        const int kb = kc * 128;
        for (int i = tid; i < 64 * 32; i += 256) {  // 64 rows x 32 float4
            int r = i >> 5, k4 = i & 31;
            float4 v = tf32r4(*(const float4*)(g_h + r * HID + kb + k4 * 4));
            *(float4*)(hs + r * 132 + k4 * 4) = v;
        }
        __syncthreads();
#pragma unroll
        for (int ks = 0; ks < 16; ks++) {
            int kk = ks * 8;
            uint32_t af[4];
            int rb = wm * 16;
            af[0] = __float_as_uint(hs[(rb + g    ) * 132 + kk + tg    ]);
            af[1] = __float_as_uint(hs[(rb + g + 8) * 132 + kk + tg    ]);
            af[2] = __float_as_uint(hs[(rb + g    ) * 132 + kk + tg + 4]);
            af[3] = __float_as_uint(hs[(rb + g + 8) * 132 + kk + tg + 4]);
#pragma unroll
            for (int nt = 0; nt < 2; nt++) {
                int cb = wn * 16 + nt * 8;
                uint32_t bf[2];
                bf[0] = __float_as_uint(ws[(cb + g) * 1028 + kb + kk + tg    ]);
                bf[1] = __float_as_uint(ws[(cb + g) * 1028 + kb + kk + tg + 4]);
                mma8(acc[nt], af, bf);
            }
        }
    }
    __syncthreads();

    // Gates to SMEM (reuse hs region): gs[64][36]
    float* gs = hs;
#pragma unroll
    for (int nt = 0; nt < 2; nt++) {
        int row = wm * 16 + g;
        int col = wn * 16 + nt * 8 + 2 * tg;
        gs[row * 36 + col]           = acc[nt][0];
        gs[row * 36 + col + 1]       = acc[nt][1];
        gs[(row + 8) * 36 + col]     = acc[nt][2];
        gs[(row + 8) * 36 + col + 1] = acc[nt][3];
    }
    __syncthreads();

    // Elementwise LSTM update for this CTA's 8 h-columns x 64 batch rows.
    const float* Xgt = g_Xg + (size_t)t * BATCH * GATE;
    for (int e = tid; e < 512; e += 256) {
        int r = e >> 3, jj = e & 7;
        int n = n0 + jj;
        float iv = gs[r * 36 + jj]      + Xgt[(size_t)r * GATE + n];
        float fv = gs[r * 36 + 8 + jj]  + Xgt[(size_t)r * GATE + 1024 + n];
        float gv = gs[r * 36 + 16 + jj] + Xgt[(size_t)r * GATE + 2048 + n];
        float ov = gs[r * 36 + 24 + jj] + Xgt[(size_t)r * GATE + 3072 + n];
        float co = g_c[r * HID + n];
        float cn = sigm(fv) * co + sigm(iv) * tanhf(gv);
        float hn = sigm(ov) * tanhf(cn);
        g_c[r * HID + n] = cn;
        g_h[r * HID + n] = hn;
        g_Hall[((size_t)t * BATCH + r) * HID + n] = hn;
    }
}

extern "C" void kernel_launch(void* const* d_in, const int* in_sizes, int n_in,
                              void* d_out, int out_size)
{
    (void)in_sizes; (void)n_in; (void)out_size;
    const float* embedded = (const float*)d_in[0];
    const float* W_ih = (const float*)d_in[1];
    const float* W_hh = (const float*)d_in[2];
    const float* b_ih = (const float*)d_in[3];
    const float* b_hh = (const float*)d_in[4];
    const float* W_fc = (const float*)d_in[5];
    const float* b_fc = (const float*)d_in[6];
    float* out = (float*)d_out;

    const int smem_gemm = (2 * 128 * 36 + 2 * 64 * 36) * 4;   // 55296 B
    const int smem_step = (32 * 1028 + 64 * 132) * 4;         // 165376 B
    cudaFuncSetAttribute(gemm_tf32<0>, cudaFuncAttributeMaxDynamicSharedMemorySize, smem_gemm);
    cudaFuncSetAttribute(gemm_tf32<1>, cudaFuncAttributeMaxDynamicSharedMemorySize, smem_gemm);
    cudaFuncSetAttribute(lstm_step,    cudaFuncAttributeMaxDynamicSharedMemorySize, smem_step);

    // 1) zero h, c
    init_state<<<(BATCH * HID + 255) / 256, 256>>>();

    // 2) Xg[t,b,:] = embedded[b,t,:] @ W_ih^T + b_ih + b_hh   (batched, parallel)
    gemm_tf32<0><<<dim3(MROWS / 128, GATE / 64), 256, smem_gemm>>>(
        embedded, W_ih, b_ih, b_hh, nullptr, EMBED);

    // 3) the recurrence: one fused kernel per time step
    for (int t = 0; t < SEQ; t++)
        lstm_step<<<128, 256, smem_step>>>(t, W_hh);

    // 4) out[b,t,:] = Hall[t,b,:] @ W_fc^T + b_fc   (batched, parallel)
    gemm_tf32<1><<<dim3(MROWS / 128, HID / 64), 256, smem_gemm>>>(
        nullptr, W_fc, b_fc, nullptr, out, HID);
}

// round 5
// speedup vs baseline: 1.5385x; 1.5385x over previous
#include <cuda_runtime.h>
#include <cstdint>
#include <math.h>

#define EMBED 512
#define HID   1024
#define GATE  4096
#define BATCH 64
#define SEQ   256
#define MROWS (SEQ*BATCH)   // 16384
#define NB    128           // persistent grid size (1 CTA/SM, all resident)

// Scratch (static device allocations — permitted; no runtime alloc).
__device__ float g_Xg[(size_t)MROWS * GATE];    // [T][B][4H] input projection + biases
__device__ float g_Hall[(size_t)MROWS * HID];   // [T][B][H] all hidden states (full fp32)
__device__ float g_hbuf[2][BATCH * HID];        // double-buffered h (tf32-rounded)
__device__ unsigned int g_bar_count;
__device__ unsigned int g_bar_gen;

__device__ __forceinline__ float tf32r(float x) {
    asm("cvt.rna.tf32.f32 %0, %0;" : "+f"(x));
    return x;
}
__device__ __forceinline__ float4 tf32r4(float4 v) {
    v.x = tf32r(v.x); v.y = tf32r(v.y); v.z = tf32r(v.z); v.w = tf32r(v.w);
    return v;
}
__device__ __forceinline__ void mma8(float* c, const uint32_t* a, const uint32_t* b) {
    asm volatile("mma.sync.aligned.m16n8k8.row.col.f32.tf32.tf32.f32 "
                 "{%0,%1,%2,%3}, {%4,%5,%6,%7}, {%8,%9}, {%0,%1,%2,%3};"
                 : "+f"(c[0]), "+f"(c[1]), "+f"(c[2]), "+f"(c[3])
                 : "r"(a[0]), "r"(a[1]), "r"(a[2]), "r"(a[3]), "r"(b[0]), "r"(b[1]));
}
__device__ __forceinline__ float sigm(float x) { return 1.f / (1.f + expf(-x)); }

__global__ void init_state() {
    int i = blockIdx.x * blockDim.x + threadIdx.x;
    if (i < BATCH * HID) g_hbuf[0][i] = 0.f;
    if (i == 0) { g_bar_count = 0u; g_bar_gen = 0u; }
}

// Software grid barrier: all NB CTAs are guaranteed co-resident (1 CTA/SM,
// NB=128 <= 148 SMs), so spinning cannot deadlock.
__device__ __forceinline__ void grid_bar() {
    __threadfence();           // order this thread's h writes before release
    __syncthreads();
    if (threadIdx.x == 0) {
        unsigned int gen = *(volatile unsigned int*)&g_bar_gen;
        if (atomicAdd(&g_bar_count, 1u) == NB - 1u) {
            g_bar_count = 0u;
            __threadfence();
            atomicExch(&g_bar_gen, gen + 1u);   // release
        } else {
            while (*(volatile unsigned int*)&g_bar_gen == gen) { }
            __threadfence();                    // acquire
        }
    }
    __syncthreads();
}

// ---------------------------------------------------------------------------
// Generic tf32 GEMM:  C[m, n] = sum_k A[m,k] * W[n,k]  (+ bias)
// MODE 0 (pre):  A = embedded gathered by (t,b) row map, C = g_Xg direct,
//                bias = b_ih + b_hh, K = 512.
// MODE 1 (post): A = g_Hall direct, C = out scattered to [B][T][H], K = 1024.
// BM=128, BN=64, BK=32, 256 threads (8 warps, 4x2), warp tile 32x32.
// ---------------------------------------------------------------------------
template<int MODE>
__launch_bounds__(256)
__global__ void gemm_tf32(const float* __restrict__ Ain,
                          const float* __restrict__ W,
                          const float* __restrict__ b1,
                          const float* __restrict__ b2,
                          float* __restrict__ Cout,
                          int K)
{
    extern __shared__ float sm[];
    float* As = sm;                 // 2 * 128*36 floats
    float* Bs = sm + 2 * 128 * 36;  // 2 * 64*36 floats

    const float* A = (MODE == 0) ? Ain : g_Hall;
    float* C       = (MODE == 0) ? g_Xg : Cout;

    const int tid  = threadIdx.x;
    const int warp = tid >> 5, lane = tid & 31;
    const int wm = warp >> 1, wn = warp & 1;
    const int g = lane >> 2, tg = lane & 3;
    const int mBase = blockIdx.x * 128;
    const int nBase = blockIdx.y * 64;
    const int nk = K >> 5;

    float acc[2][4][4];
#pragma unroll
    for (int a = 0; a < 2; a++)
#pragma unroll
        for (int b = 0; b < 4; b++)
#pragma unroll
            for (int cc = 0; cc < 4; cc++) acc[a][b][cc] = 0.f;

    float4 ar[4], br[2];

    // prologue: load k-tile 0 and stage to buffer 0
    {
#pragma unroll
        for (int i = 0; i < 4; i++) {
            int idx = tid + i * 256;
            int r = idx >> 3, k4 = idx & 7;
            int m = mBase + r;
            size_t aoff = (MODE == 0) ? ((size_t)((m & 63) * SEQ + (m >> 6)) * EMBED)
                                      : ((size_t)m * HID);
            ar[i] = *(const float4*)(A + aoff + k4 * 4);
        }
#pragma unroll
        for (int i = 0; i < 2; i++) {
            int idx = tid + i * 256;
            int r = idx >> 3, k4 = idx & 7;
            br[i] = *(const float4*)(W + (size_t)(nBase + r) * K + k4 * 4);
        }
#pragma unroll
        for (int i = 0; i < 4; i++) {
            int idx = tid + i * 256; int r = idx >> 3, k4 = idx & 7;
            *(float4*)(As + r * 36 + k4 * 4) = tf32r4(ar[i]);
        }
#pragma unroll
        for (int i = 0; i < 2; i++) {
            int idx = tid + i * 256; int r = idx >> 3, k4 = idx & 7;
            *(float4*)(Bs + r * 36 + k4 * 4) = tf32r4(br[i]);
        }
    }
    __syncthreads();

    for (int kt = 0; kt < nk; kt++) {
        if (kt + 1 < nk) {
            const int kB = (kt + 1) * 32;
#pragma unroll
            for (int i = 0; i < 4; i++) {
                int idx = tid + i * 256;
                int r = idx >> 3, k4 = idx & 7;
                int m = mBase + r;
                size_t aoff = (MODE == 0) ? ((size_t)((m & 63) * SEQ + (m >> 6)) * EMBED)
                                          : ((size_t)m * HID);
                ar[i] = *(const float4*)(A + aoff + kB + k4 * 4);
            }
#pragma unroll
            for (int i = 0; i < 2; i++) {
                int idx = tid + i * 256;
                int r = idx >> 3, k4 = idx & 7;
                br[i] = *(const float4*)(W + (size_t)(nBase + r) * K + kB + k4 * 4);
            }
        }
        const float* as = As + (kt & 1) * (128 * 36);
        const float* bs = Bs + (kt & 1) * (64 * 36);
#pragma unroll
        for (int ks = 0; ks < 4; ks++) {
            const int kk = ks * 8;
            uint32_t af[2][4], bf[4][2];
#pragma unroll
            for (int mt = 0; mt < 2; mt++) {
                int rb = wm * 32 + mt * 16;
                af[mt][0] = __float_as_uint(as[(rb + g    ) * 36 + kk + tg    ]);
                af[mt][1] = __float_as_uint(as[(rb + g + 8) * 36 + kk + tg    ]);
                af[mt][2] = __float_as_uint(as[(rb + g    ) * 36 + kk + tg + 4]);
                af[mt][3] = __float_as_uint(as[(rb + g + 8) * 36 + kk + tg + 4]);
            }
#pragma unroll
            for (int nt = 0; nt < 4; nt++) {
                int cb = wn * 32 + nt * 8;
                bf[nt][0] = __float_as_uint(bs[(cb + g) * 36 + kk + tg    ]);
                bf[nt][1] = __float_as_uint(bs[(cb + g) * 36 + kk + tg + 4]);
            }
#pragma unroll
            for (int mt = 0; mt < 2; mt++)
#pragma unroll
                for (int nt = 0; nt < 4; nt++)
                    mma8(acc[mt][nt], af[mt], bf[nt]);
        }
        if (kt + 1 < nk) {
            float* as2 = As + ((kt + 1) & 1) * (128 * 36);
            float* bs2 = Bs + ((kt + 1) & 1) * (64 * 36);
#pragma unroll
            for (int i = 0; i < 4; i++) {
                int idx = tid + i * 256; int r = idx >> 3, k4 = idx & 7;
                *(float4*)(as2 + r * 36 + k4 * 4) = tf32r4(ar[i]);
            }
#pragma unroll
            for (int i = 0; i < 2; i++) {
                int idx = tid + i * 256; int r = idx >> 3, k4 = idx & 7;
                *(float4*)(bs2 + r * 36 + k4 * 4) = tf32r4(br[i]);
            }
        }
        __syncthreads();
    }

    // epilogue: bias + store
#pragma unroll
    for (int mt = 0; mt < 2; mt++) {
#pragma unroll
        for (int nt = 0; nt < 4; nt++) {
            int row = mBase + wm * 32 + mt * 16 + g;
            int col = nBase + wn * 32 + nt * 8 + 2 * tg;
            float bv0 = b1[col], bv1 = b1[col + 1];
            if (MODE == 0) { bv0 += b2[col]; bv1 += b2[col + 1]; }
            size_t c0off, c2off;
            if (MODE == 0) {
                c0off = (size_t)row * GATE + col;
                c2off = (size_t)(row + 8) * GATE + col;
            } else {
                c0off = (size_t)((row & 63) * SEQ + (row >> 6)) * HID + col;
                c2off = (size_t)(((row + 8) & 63) * SEQ + ((row + 8) >> 6)) * HID + col;
            }
            *(float2*)(C + c0off) = make_float2(acc[mt][nt][0] + bv0, acc[mt][nt][1] + bv1);
            *(float2*)(C + c2off) = make_float2(acc[mt][nt][2] + bv0, acc[mt][nt][3] + bv1);
        }
    }
}

// ---------------------------------------------------------------------------
// Persistent LSTM recurrence: 128 CTAs, each owns 8 h-columns (=> 32 gate
// columns). W_hh slice (32x1024) staged into SMEM ONCE; c kept in registers
// for all 256 steps; h double-buffered in global with one grid barrier/step.
// h is stored pre-rounded to tf32 (value-identical to rounding at stage time),
// so the per-chunk h staging is a pure copy, register-double-buffered.
// ---------------------------------------------------------------------------
__launch_bounds__(256, 1)
__global__ void lstm_persist(const float* __restrict__ Whh)
{
    extern __shared__ float sm[];
    float* ws = sm;                  // 32 rows * 1028 floats (resident W slice)
    float* hs = sm + 32 * 1028;      // 2 * 64 * 132 floats (h chunk, dbl-buffered)

    const int tid  = threadIdx.x;
    const int warp = tid >> 5, lane = tid & 31;
    const int wm = warp >> 1, wn = warp & 1;
    const int g = lane >> 2, tg = lane & 3;
    const int n0 = blockIdx.x * 8;

    // Stage W_hh slice (rows {n0+j, 1024+n0+j, 2048+n0+j, 3072+n0+j}), tf32.
    for (int i = tid; i < 32 * 256; i += 256) {
        int j = i >> 8, k4 = i & 255;
        int grow = (j >> 3) * HID + n0 + (j & 7);
        float4 v = tf32r4(*(const float4*)(Whh + (size_t)grow * HID + k4 * 4));
        *(float4*)(ws + j * 1028 + k4 * 4) = v;
    }

    // Per-thread elementwise mapping: elements (r0, j) and (r0+32, j), same n.
    const int r0 = tid >> 3, j0 = tid & 7;
    const int n  = n0 + j0;
    float c0 = 0.f, c1 = 0.f;       // cell state lives in registers

    for (int t = 0; t < SEQ; t++) {
        const int p = t & 1;
        const float* __restrict__ hin = g_hbuf[p];
        float* __restrict__ hout = g_hbuf[p ^ 1];
        const float* __restrict__ Xgt = g_Xg + (size_t)t * BATCH * GATE;

        // Prefetch Xg gate biases (overlaps the whole MMA loop).
        float xi0 = Xgt[(size_t)r0 * GATE + n];
        float xf0 = Xgt[(size_t)r0 * GATE + 1024 + n];
        float xg0 = Xgt[(size_t)r0 * GATE + 2048 + n];
        float xo0 = Xgt[(size_t)r0 * GATE + 3072 + n];
        float xi1 = Xgt[(size_t)(r0 + 32) * GATE + n];
        float xf1 = Xgt[(size_t)(r0 + 32) * GATE + 1024 + n];
        float xg1 = Xgt[(size_t)(r0 + 32) * GATE + 2048 + n];
        float xo1 = Xgt[(size_t)(r0 + 32) * GATE + 3072 + n];

        float acc[2][4];
#pragma unroll
        for (int nt = 0; nt < 2; nt++)
#pragma unroll
            for (int cc = 0; cc < 4; cc++) acc[nt][cc] = 0.f;

        // h chunk 0 prologue (pure copy — h already tf32-rounded)
        float4 hr[8];
        {
#pragma unroll
            for (int i = 0; i < 8; i++) {
                int idx = tid + i * 256; int r = idx >> 5, k4 = idx & 31;
                hr[i] = *(const float4*)(hin + r * HID + k4 * 4);
            }
#pragma unroll
            for (int i = 0; i < 8; i++) {
                int idx = tid + i * 256; int r = idx >> 5, k4 = idx & 31;
                *(float4*)(hs + r * 132 + k4 * 4) = hr[i];
            }
        }
        __syncthreads();

        for (int kc = 0; kc < 8; kc++) {
            if (kc < 7) {
                const int kB = (kc + 1) * 128;
#pragma unroll
                for (int i = 0; i < 8; i++) {
                    int idx = tid + i * 256; int r = idx >> 5, k4 = idx & 31;
                    hr[i] = *(const float4*)(hin + r * HID + kB + k4 * 4);
                }
            }
            const float* hsb = hs + (kc & 1) * (64 * 132);
            const int kb = kc * 128;
#pragma unroll
            for (int ks = 0; ks < 16; ks++) {
                int kk = ks * 8;
                uint32_t af[4];
                int rb = wm * 16;
                af[0] = __float_as_uint(hsb[(rb + g    ) * 132 + kk + tg    ]);
                af[1] = __float_as_uint(hsb[(rb + g + 8) * 132 + kk + tg    ]);
                af[2] = __float_as_uint(hsb[(rb + g    ) * 132 + kk + tg + 4]);
                af[3] = __float_as_uint(hsb[(rb + g + 8) * 132 + kk + tg + 4]);
#pragma unroll
                for (int nt = 0; nt < 2; nt++) {
                    int cb = wn * 16 + nt * 8;
                    uint32_t bf[2];
                    bf[0] = __float_as_uint(ws[(cb + g) * 1028 + kb + kk + tg    ]);
                    bf[1] = __float_as_uint(ws[(cb + g) * 1028 + kb + kk + tg + 4]);
                    mma8(acc[nt], af, bf);
                }
            }
            if (kc < 7) {
                float* hsd = hs + ((kc + 1) & 1) * (64 * 132);
#pragma unroll
                for (int i = 0; i < 8; i++) {
                    int idx = tid + i * 256; int r = idx >> 5, k4 = idx & 31;
                    *(float4*)(hsd + r * 132 + k4 * 4) = hr[i];
                }
            }
            __syncthreads();
        }

        // Gates to SMEM (reuse hs buffer 0): gs[64][36]
        float* gs = hs;
#pragma unroll
        for (int nt = 0; nt < 2; nt++) {
            int row = wm * 16 + g;
            int col = wn * 16 + nt * 8 + 2 * tg;
            gs[row * 36 + col]           = acc[nt][0];
            gs[row * 36 + col + 1]       = acc[nt][1];
            gs[(row + 8) * 36 + col]     = acc[nt][2];
            gs[(row + 8) * 36 + col + 1] = acc[nt][3];
        }
        __syncthreads();

        // Elementwise LSTM update (2 cells per thread, c in registers).
        {
            float iv = gs[r0 * 36 + j0]      + xi0;
            float fv = gs[r0 * 36 + 8 + j0]  + xf0;
            float gv = gs[r0 * 36 + 16 + j0] + xg0;
            float ov = gs[r0 * 36 + 24 + j0] + xo0;
            c0 = sigm(fv) * c0 + sigm(iv) * tanhf(gv);
            float hn = sigm(ov) * tanhf(c0);
            hout[r0 * HID + n] = tf32r(hn);
            g_Hall[((size_t)t * BATCH + r0) * HID + n] = hn;

            int r1 = r0 + 32;
            iv = gs[r1 * 36 + j0]      + xi1;
            fv = gs[r1 * 36 + 8 + j0]  + xf1;
            gv = gs[r1 * 36 + 16 + j0] + xg1;
            ov = gs[r1 * 36 + 24 + j0] + xo1;
            c1 = sigm(fv) * c1 + sigm(iv) * tanhf(gv);
            hn = sigm(ov) * tanhf(c1);
            hout[r1 * HID + n] = tf32r(hn);
            g_Hall[((size_t)t * BATCH + r1) * HID + n] = hn;
        }

        grid_bar();   // h(t) visible everywhere before step t+1 reads it
    }
}

extern "C" void kernel_launch(void* const* d_in, const int* in_sizes, int n_in,
                              void* d_out, int out_size)
{
    (void)in_sizes; (void)n_in; (void)out_size;
    const float* embedded = (const float*)d_in[0];
    const float* W_ih = (const float*)d_in[1];
    const float* W_hh = (const float*)d_in[2];
    const float* b_ih = (const float*)d_in[3];
    const float* b_hh = (const float*)d_in[4];
    const float* W_fc = (const float*)d_in[5];
    const float* b_fc = (const float*)d_in[6];
    float* out = (float*)d_out;

    const int smem_gemm = (2 * 128 * 36 + 2 * 64 * 36) * 4;     // 55296 B
    const int smem_pers = (32 * 1028 + 2 * 64 * 132) * 4;       // 199168 B
    cudaFuncSetAttribute(gemm_tf32<0>, cudaFuncAttributeMaxDynamicSharedMemorySize, smem_gemm);
    cudaFuncSetAttribute(gemm_tf32<1>, cudaFuncAttributeMaxDynamicSharedMemorySize, smem_gemm);
    cudaFuncSetAttribute(lstm_persist, cudaFuncAttributeMaxDynamicSharedMemorySize, smem_pers);

    // 1) zero h(0), reset grid barrier
    init_state<<<(BATCH * HID + 255) / 256, 256>>>();

    // 2) Xg[t,b,:] = embedded[b,t,:] @ W_ih^T + b_ih + b_hh
    gemm_tf32<0><<<dim3(MROWS / 128, GATE / 64), 256, smem_gemm>>>(
        embedded, W_ih, b_ih, b_hh, nullptr, EMBED);

    // 3) the whole recurrence: ONE persistent kernel, W_hh resident in SMEM
    lstm_persist<<<NB, 256, smem_pers>>>(W_hh);

    // 4) out[b,t,:] = Hall[t,b,:] @ W_fc^T + b_fc
    gemm_tf32<1><<<dim3(MROWS / 128, HID / 64), 256, smem_gemm>>>(
        nullptr, W_fc, b_fc, nullptr, out, HID);
}